// round 8
// baseline (speedup 1.0000x reference)
#include <cuda_runtime.h>

#define N_USER   100000
#define N_ITEM   100000
#define N_NODE2  200000          // combined dst space: [0,100K)=item(u2i), [100K,200K)=user(i2u)
#define N_EDGE   1600000
#define N_EDGE2  3200000
#define IN_DIM   128
#define OUT_DIM  64
#define NEG_SLOPE 0.01f
#define LROWS    32
#define NBLK_SCAN 196            // ceil(200000/1024)

// ---------------- device scratch (static, no runtime alloc) ----------------
__device__ float  g_Wh_user[(size_t)N_USER * OUT_DIM];   // 25.6 MB
__device__ float  g_Wh_item[(size_t)N_ITEM * OUT_DIM];   // 25.6 MB
__device__ float  g_su_src[N_USER];
__device__ float  g_su_dst[N_USER];
__device__ float  g_si_src[N_ITEM];
__device__ float  g_si_dst[N_ITEM];
__device__ int    g_cnt[N_NODE2];
__device__ int    g_offs[N_NODE2];
__device__ int    g_cursor[N_NODE2];
__device__ int    g_bsum[NBLK_SCAN];
__device__ int    g_boff[NBLK_SCAN];
__device__ float2 g_csr[N_EDGE2];     // packed (src_as_float, ex), 25.6 MB

// ---------------- per-replay reset: degree counters ----------------
__global__ __launch_bounds__(256) void zero_kernel(int* __restrict__ cnt)
{
    int i = blockIdx.x * blockDim.x + threadIdx.x;
    if (i < N_NODE2) cnt[i] = 0;
}

// ------- Wh = feat @ W + b fused with s_src/s_dst epilogue -------
// thread = 2 cols x 4 rows (round-7 proven mapping); k stepped by 4 with
// LDS.128 feature loads -> 8 LDS + 32 FFMA per k-quad (80% FMA issue).
__global__ __launch_bounds__(256) void linear_attn_kernel(
    const float* __restrict__ feat, const float* __restrict__ W,
    const float* __restrict__ b, const float* __restrict__ attn,
    float* __restrict__ Wh, float* __restrict__ s_src, float* __restrict__ s_dst)
{
    __shared__ float Ws[IN_DIM * OUT_DIM];   // 32 KB
    __shared__ float fs[LROWS][IN_DIM];      // 16 KB (reused for Wh tile)
    int tid = threadIdx.x;

    #pragma unroll
    for (int i = tid; i < IN_DIM * OUT_DIM; i += 256) Ws[i] = W[i];

    int row0 = blockIdx.x * LROWS;
    const float4* fsrc = reinterpret_cast<const float4*>(feat + (size_t)row0 * IN_DIM);
    float4* fdst = reinterpret_cast<float4*>(&fs[0][0]);
    #pragma unroll
    for (int i = tid; i < LROWS * IN_DIM / 4; i += 256) fdst[i] = fsrc[i];
    __syncthreads();

    int cg = tid & 31;   // column pair index
    int rg = tid >> 5;   // row group (4 rows)
    const float2* Ws2 = reinterpret_cast<const float2*>(Ws);
    const float4* f0_4 = reinterpret_cast<const float4*>(&fs[rg * 4 + 0][0]);
    const float4* f1_4 = reinterpret_cast<const float4*>(&fs[rg * 4 + 1][0]);
    const float4* f2_4 = reinterpret_cast<const float4*>(&fs[rg * 4 + 2][0]);
    const float4* f3_4 = reinterpret_cast<const float4*>(&fs[rg * 4 + 3][0]);

    float2 acc[4] = {{0.f,0.f},{0.f,0.f},{0.f,0.f},{0.f,0.f}};

    #pragma unroll 2
    for (int k4 = 0; k4 < IN_DIM / 4; k4++) {
        float4 f0 = f0_4[k4];
        float4 f1 = f1_4[k4];
        float4 f2 = f2_4[k4];
        float4 f3 = f3_4[k4];
        float2 w0 = Ws2[(k4 * 4 + 0) * 32 + cg];
        float2 w1 = Ws2[(k4 * 4 + 1) * 32 + cg];
        float2 w2 = Ws2[(k4 * 4 + 2) * 32 + cg];
        float2 w3 = Ws2[(k4 * 4 + 3) * 32 + cg];

        acc[0].x = fmaf(f0.x, w0.x, acc[0].x); acc[0].y = fmaf(f0.x, w0.y, acc[0].y);
        acc[1].x = fmaf(f1.x, w0.x, acc[1].x); acc[1].y = fmaf(f1.x, w0.y, acc[1].y);
        acc[2].x = fmaf(f2.x, w0.x, acc[2].x); acc[2].y = fmaf(f2.x, w0.y, acc[2].y);
        acc[3].x = fmaf(f3.x, w0.x, acc[3].x); acc[3].y = fmaf(f3.x, w0.y, acc[3].y);

        acc[0].x = fmaf(f0.y, w1.x, acc[0].x); acc[0].y = fmaf(f0.y, w1.y, acc[0].y);
        acc[1].x = fmaf(f1.y, w1.x, acc[1].x); acc[1].y = fmaf(f1.y, w1.y, acc[1].y);
        acc[2].x = fmaf(f2.y, w1.x, acc[2].x); acc[2].y = fmaf(f2.y, w1.y, acc[2].y);
        acc[3].x = fmaf(f3.y, w1.x, acc[3].x); acc[3].y = fmaf(f3.y, w1.y, acc[3].y);

        acc[0].x = fmaf(f0.z, w2.x, acc[0].x); acc[0].y = fmaf(f0.z, w2.y, acc[0].y);
        acc[1].x = fmaf(f1.z, w2.x, acc[1].x); acc[1].y = fmaf(f1.z, w2.y, acc[1].y);
        acc[2].x = fmaf(f2.z, w2.x, acc[2].x); acc[2].y = fmaf(f2.z, w2.y, acc[2].y);
        acc[3].x = fmaf(f3.z, w2.x, acc[3].x); acc[3].y = fmaf(f3.z, w2.y, acc[3].y);

        acc[0].x = fmaf(f0.w, w3.x, acc[0].x); acc[0].y = fmaf(f0.w, w3.y, acc[0].y);
        acc[1].x = fmaf(f1.w, w3.x, acc[1].x); acc[1].y = fmaf(f1.w, w3.y, acc[1].y);
        acc[2].x = fmaf(f2.w, w3.x, acc[2].x); acc[2].y = fmaf(f2.w, w3.y, acc[2].y);
        acc[3].x = fmaf(f3.w, w3.x, acc[3].x); acc[3].y = fmaf(f3.w, w3.y, acc[3].y);
    }

    float2 b2 = reinterpret_cast<const float2*>(b)[cg];
    __syncthreads();   // done reading fs; reuse as Wh tile
    float2* sWh2 = reinterpret_cast<float2*>(&fs[0][0]);   // [32][32] float2
    #pragma unroll
    for (int r = 0; r < 4; r++) {
        acc[r].x += b2.x; acc[r].y += b2.y;
        int row = rg * 4 + r;
        reinterpret_cast<float2*>(Wh)[(size_t)(row0 + row) * 32 + cg] = acc[r];
        sWh2[row * 32 + cg] = acc[r];
    }
    __syncthreads();

    // epilogue: 8 warps x 4 rows
    int wid = tid >> 5, lane = tid & 31;
    float a0 = attn[lane],      a1 = attn[lane + 32];
    float c0 = attn[64 + lane], c1 = attn[96 + lane];
    const float* sWh = &fs[0][0];
    #pragma unroll
    for (int rr = 0; rr < 4; rr++) {
        int row = wid * 4 + rr;
        float v0 = sWh[row * 64 + lane];
        float v1 = sWh[row * 64 + lane + 32];
        float ps = fmaf(v0, a0, v1 * a1);
        float pd = fmaf(v0, c0, v1 * c1);
        #pragma unroll
        for (int o = 16; o; o >>= 1) {
            ps += __shfl_xor_sync(0xffffffffu, ps, o);
            pd += __shfl_xor_sync(0xffffffffu, pd, o);
        }
        if (lane == 0) { s_src[row0 + row] = ps; s_dst[row0 + row] = pd; }
    }
}

// ---------------- histogram of dst degrees, both etypes (4 edges/thread) ----
__global__ __launch_bounds__(256) void hist_kernel(const int4* __restrict__ dstA4,
                                                   const int4* __restrict__ dstB4,
                                                   int* __restrict__ cnt)
{
    int i = blockIdx.x * blockDim.x + threadIdx.x;
    const int nq = N_EDGE / 4;
    if (i >= 2 * nq) return;
    bool second = i >= nq;
    int4 d = second ? dstB4[i - nq] : dstA4[i];
    int gbase = second ? N_ITEM : 0;
    atomicAdd(&cnt[gbase + d.x], 1);
    atomicAdd(&cnt[gbase + d.y], 1);
    atomicAdd(&cnt[gbase + d.z], 1);
    atomicAdd(&cnt[gbase + d.w], 1);
}

// ---------------- exclusive scan (3 kernels) ----------------
__global__ __launch_bounds__(256) void scan1_kernel(const int* __restrict__ cnt,
        int* __restrict__ offs, int* __restrict__ bsum)
{
    __shared__ int wsum[8];
    int tid = threadIdx.x;
    int base = blockIdx.x * 1024 + tid * 4;
    int v[4];
    #pragma unroll
    for (int q = 0; q < 4; q++) { int i = base + q; v[q] = (i < N_NODE2) ? cnt[i] : 0; }
    int t = v[0] + v[1] + v[2] + v[3];
    int lane = tid & 31, wid = tid >> 5;
    int inc = t;
    #pragma unroll
    for (int o = 1; o < 32; o <<= 1) { int n = __shfl_up_sync(0xffffffffu, inc, o); if (lane >= o) inc += n; }
    if (lane == 31) wsum[wid] = inc;
    __syncthreads();
    if (wid == 0) {
        int ws = (lane < 8) ? wsum[lane] : 0;
        int winc = ws;
        #pragma unroll
        for (int o = 1; o < 8; o <<= 1) { int n = __shfl_up_sync(0xffffffffu, winc, o); if (lane >= o) winc += n; }
        if (lane < 8) wsum[lane] = winc - ws;          // exclusive warp offsets
        if (lane == 7) bsum[blockIdx.x] = winc;        // block total
    }
    __syncthreads();
    int run = wsum[wid] + (inc - t);
    #pragma unroll
    for (int q = 0; q < 4; q++) { int i = base + q; if (i < N_NODE2) offs[i] = run; run += v[q]; }
}

__global__ __launch_bounds__(256) void scan2_kernel(const int* __restrict__ bsum,
                                                    int* __restrict__ boff)
{
    __shared__ int wsum[8];
    int tid = threadIdx.x;
    int v = (tid < NBLK_SCAN) ? bsum[tid] : 0;
    int lane = tid & 31, wid = tid >> 5;
    int inc = v;
    #pragma unroll
    for (int o = 1; o < 32; o <<= 1) { int n = __shfl_up_sync(0xffffffffu, inc, o); if (lane >= o) inc += n; }
    if (lane == 31) wsum[wid] = inc;
    __syncthreads();
    if (wid == 0) {
        int ws = (lane < 8) ? wsum[lane] : 0;
        int winc = ws;
        #pragma unroll
        for (int o = 1; o < 8; o <<= 1) { int n = __shfl_up_sync(0xffffffffu, winc, o); if (lane >= o) winc += n; }
        if (lane < 8) wsum[lane] = winc - ws;
    }
    __syncthreads();
    if (tid < NBLK_SCAN) boff[tid] = wsum[wid] + (inc - v);
}

__global__ __launch_bounds__(256) void scan3_kernel(int* __restrict__ offs,
        const int* __restrict__ boff, int* __restrict__ cursor)
{
    int i = blockIdx.x * blockDim.x + threadIdx.x;
    if (i >= N_NODE2) return;
    int o = offs[i] + boff[i >> 10];
    offs[i] = o;
    cursor[i] = o;
}

// --------- scatter (both etypes, 2 edges/thread): csr[pos] = (src, ex) ---------
__global__ __launch_bounds__(256) void scatter_kernel(
    const int2* __restrict__ srcA2, const int2* __restrict__ dstA2,
    const int2* __restrict__ srcB2, const int2* __restrict__ dstB2,
    const float* __restrict__ su_src, const float* __restrict__ su_dst,
    const float* __restrict__ si_src, const float* __restrict__ si_dst,
    int* __restrict__ cursor, float2* __restrict__ csr)
{
    int t = blockIdx.x * blockDim.x + threadIdx.x;
    const int nh = N_EDGE / 2;
    if (t >= 2 * nh) return;
    bool second = t >= nh;
    int e2 = second ? t - nh : t;
    int2 s2 = second ? srcB2[e2] : srcA2[e2];
    int2 d2 = second ? dstB2[e2] : dstA2[e2];
    const float* ssrc = second ? si_src : su_src;
    const float* sdst = second ? su_dst : si_dst;
    int gbase = second ? N_ITEM : 0;

    float vs0 = ssrc[s2.x], vs1 = ssrc[s2.y];
    float vd0 = sdst[d2.x], vd1 = sdst[d2.y];
    float v0 = vs0 + vd0;  v0 = v0 > 0.f ? v0 : NEG_SLOPE * v0;
    float v1 = vs1 + vd1;  v1 = v1 > 0.f ? v1 : NEG_SLOPE * v1;
    float ex0 = __expf(v0), ex1 = __expf(v1);

    int pos0 = atomicAdd(&cursor[gbase + d2.x], 1);
    int pos1 = atomicAdd(&cursor[gbase + d2.y], 1);
    csr[pos0] = make_float2(__int_as_float(s2.x), ex0);
    csr[pos1] = make_float2(__int_as_float(s2.y), ex1);
}

// --------- aggregate: warp per dst node; unroll-16 inner groups --------
// avg degree ~16 -> one group covers the typical node; 16 predicated LDG.64
// in flight. Padded lanes carry ex=0; the ej!=0 predicate kills their traffic.
__global__ __launch_bounds__(256) void agg_kernel(
    const int* __restrict__ offs, const float2* __restrict__ csr,
    const float2* __restrict__ Whu2, const float2* __restrict__ Whi2,
    float2* __restrict__ out2)
{
    int g = (blockIdx.x * 256 + threadIdx.x) >> 5;
    int lane = threadIdx.x & 31;
    if (g >= N_NODE2) return;

    int beg = offs[g];
    int end = (g == N_NODE2 - 1) ? N_EDGE2 : offs[g + 1];
    const float2* Wh2 = (g < N_ITEM) ? Whu2 : Whi2;            // item-dst <- user src
    int orow = (g < N_ITEM) ? (N_USER + g) : (g - N_ITEM);

    float2 acc = make_float2(0.f, 0.f);
    float den = 0.f;

    for (int k0 = beg; k0 < end; k0 += 32) {
        int k = k0 + lane;
        float2 p = (k < end) ? csr[k] : make_float2(0.f, 0.f);  // pad: s=0(valid), ex=0
        int   s  = __float_as_int(p.x);
        float ex = p.y;
        int m = end - k0; if (m > 32) m = 32;
        for (int j0 = 0; j0 < m; j0 += 16) {
            #pragma unroll
            for (int jj = 0; jj < 16; jj++) {
                int   sj = __shfl_sync(0xffffffffu, s,  j0 + jj);
                float ej = __shfl_sync(0xffffffffu, ex, j0 + jj);
                if (ej != 0.f) {
                    float2 z = Wh2[(size_t)sj * 32 + lane];
                    acc.x = fmaf(ej, z.x, acc.x);
                    acc.y = fmaf(ej, z.y, acc.y);
                    den += ej;
                }
            }
        }
    }
    if (end > beg) {
        float inv = 1.f / den;
        acc.x *= inv; acc.y *= inv;
    }
    out2[(size_t)orow * 32 + lane] = acc;
}

// ---------------- launch ----------------
extern "C" void kernel_launch(void* const* d_in, const int* in_sizes, int n_in,
                              void* d_out, int out_size)
{
    const float* feat_user = (const float*)d_in[0];
    const float* feat_item = (const float*)d_in[1];
    const float* W_user    = (const float*)d_in[2];
    const float* b_user    = (const float*)d_in[3];
    const float* W_item    = (const float*)d_in[4];
    const float* b_item    = (const float*)d_in[5];
    const float* attn_w    = (const float*)d_in[6];
    const int*   src_u2i   = (const int*)d_in[7];
    const int*   dst_u2i   = (const int*)d_in[8];
    const int*   src_i2u   = (const int*)d_in[9];
    const int*   dst_i2u   = (const int*)d_in[10];
    float* out = (float*)d_out;

    // true DEVICE addresses of __device__ globals (host-shadow/ATS trap!)
    float *Wh_user, *Wh_item, *su_src, *su_dst, *si_src, *si_dst;
    float2 *csr;
    int *cnt, *offs, *cursor, *bsum, *boff;
    cudaGetSymbolAddress((void**)&Wh_user, g_Wh_user);
    cudaGetSymbolAddress((void**)&Wh_item, g_Wh_item);
    cudaGetSymbolAddress((void**)&su_src,  g_su_src);
    cudaGetSymbolAddress((void**)&su_dst,  g_su_dst);
    cudaGetSymbolAddress((void**)&si_src,  g_si_src);
    cudaGetSymbolAddress((void**)&si_dst,  g_si_dst);
    cudaGetSymbolAddress((void**)&cnt,     g_cnt);
    cudaGetSymbolAddress((void**)&offs,    g_offs);
    cudaGetSymbolAddress((void**)&cursor,  g_cursor);
    cudaGetSymbolAddress((void**)&bsum,    g_bsum);
    cudaGetSymbolAddress((void**)&boff,    g_boff);
    cudaGetSymbolAddress((void**)&csr,     g_csr);

    zero_kernel<<<(N_NODE2 + 255) / 256, 256>>>(cnt);

    linear_attn_kernel<<<N_USER / LROWS, 256>>>(feat_user, W_user, b_user, attn_w,
                                                Wh_user, su_src, su_dst);
    linear_attn_kernel<<<N_ITEM / LROWS, 256>>>(feat_item, W_item, b_item, attn_w,
                                                Wh_item, si_src, si_dst);

    hist_kernel<<<(2 * (N_EDGE / 4) + 255) / 256, 256>>>(
        (const int4*)dst_u2i, (const int4*)dst_i2u, cnt);

    scan1_kernel<<<NBLK_SCAN, 256>>>(cnt, offs, bsum);
    scan2_kernel<<<1, 256>>>(bsum, boff);
    scan3_kernel<<<(N_NODE2 + 255) / 256, 256>>>(offs, boff, cursor);

    scatter_kernel<<<(2 * (N_EDGE / 2) + 255) / 256, 256>>>(
        (const int2*)src_u2i, (const int2*)dst_u2i,
        (const int2*)src_i2u, (const int2*)dst_i2u,
        su_src, su_dst, si_src, si_dst, cursor, csr);

    agg_kernel<<<(N_NODE2 * 32 + 255) / 256, 256>>>(offs, csr,
                                                    (const float2*)Wh_user,
                                                    (const float2*)Wh_item,
                                                    (float2*)out);
}

// round 9
// speedup vs baseline: 1.0290x; 1.0290x over previous
#include <cuda_runtime.h>

#define N_USER   100000
#define N_ITEM   100000
#define N_NODE2  200000          // combined dst space: [0,100K)=item(u2i), [100K,200K)=user(i2u)
#define N_EDGE   1600000
#define N_EDGE2  3200000
#define IN_DIM   128
#define OUT_DIM  64
#define NEG_SLOPE 0.01f
#define LROWS    32
#define NBLK_SCAN 196            // ceil(200000/1024)

// ---------------- device scratch (static, no runtime alloc) ----------------
__device__ float  g_Wh_user[(size_t)N_USER * OUT_DIM];   // 25.6 MB
__device__ float  g_Wh_item[(size_t)N_ITEM * OUT_DIM];   // 25.6 MB
__device__ float  g_su_src[N_USER];
__device__ float  g_su_dst[N_USER];
__device__ float  g_si_src[N_ITEM];
__device__ float  g_si_dst[N_ITEM];
__device__ int    g_cnt[N_NODE2];
__device__ int    g_offs[N_NODE2];
__device__ int    g_cursor[N_NODE2];
__device__ int    g_bsum[NBLK_SCAN];
__device__ int    g_boff[NBLK_SCAN];
__device__ float2 g_csr[N_EDGE2];     // packed (src_as_float, ex), 25.6 MB

// ---------------- per-replay reset: degree counters ----------------
__global__ __launch_bounds__(256) void zero_kernel(int* __restrict__ cnt)
{
    int i = blockIdx.x * blockDim.x + threadIdx.x;
    if (i < N_NODE2) cnt[i] = 0;
}

// ------- Wh = feat @ W + b fused with s_src/s_dst epilogue -------
// (round-7 measured-best tile: thread = 2 cols x 4 rows; at FP32 FMA floor)
__global__ __launch_bounds__(256) void linear_attn_kernel(
    const float* __restrict__ feat, const float* __restrict__ W,
    const float* __restrict__ b, const float* __restrict__ attn,
    float* __restrict__ Wh, float* __restrict__ s_src, float* __restrict__ s_dst)
{
    __shared__ float Ws[IN_DIM * OUT_DIM];   // 32 KB
    __shared__ float fs[LROWS][IN_DIM];      // 16 KB (reused for Wh tile)
    int tid = threadIdx.x;

    #pragma unroll
    for (int i = tid; i < IN_DIM * OUT_DIM; i += 256) Ws[i] = W[i];

    int row0 = blockIdx.x * LROWS;
    const float4* fsrc = reinterpret_cast<const float4*>(feat + (size_t)row0 * IN_DIM);
    float4* fdst = reinterpret_cast<float4*>(&fs[0][0]);
    #pragma unroll
    for (int i = tid; i < LROWS * IN_DIM / 4; i += 256) fdst[i] = fsrc[i];
    __syncthreads();

    int cg = tid & 31;   // column pair index
    int rg = tid >> 5;   // row group (4 rows)
    const float2* Ws2 = reinterpret_cast<const float2*>(Ws);
    float2 acc[4] = {{0.f,0.f},{0.f,0.f},{0.f,0.f},{0.f,0.f}};

    #pragma unroll 8
    for (int k = 0; k < IN_DIM; k++) {
        float2 w = Ws2[k * 32 + cg];
        #pragma unroll
        for (int r = 0; r < 4; r++) {
            float f = fs[rg * 4 + r][k];
            acc[r].x = fmaf(f, w.x, acc[r].x);
            acc[r].y = fmaf(f, w.y, acc[r].y);
        }
    }

    float2 b2 = reinterpret_cast<const float2*>(b)[cg];
    __syncthreads();   // done reading fs; reuse as Wh tile
    float2* sWh2 = reinterpret_cast<float2*>(&fs[0][0]);   // [32][32] float2
    #pragma unroll
    for (int r = 0; r < 4; r++) {
        acc[r].x += b2.x; acc[r].y += b2.y;
        int row = rg * 4 + r;
        reinterpret_cast<float2*>(Wh)[(size_t)(row0 + row) * 32 + cg] = acc[r];
        sWh2[row * 32 + cg] = acc[r];
    }
    __syncthreads();

    // epilogue: 8 warps x 4 rows
    int wid = tid >> 5, lane = tid & 31;
    float a0 = attn[lane],      a1 = attn[lane + 32];
    float c0 = attn[64 + lane], c1 = attn[96 + lane];
    const float* sWh = &fs[0][0];
    #pragma unroll
    for (int rr = 0; rr < 4; rr++) {
        int row = wid * 4 + rr;
        float v0 = sWh[row * 64 + lane];
        float v1 = sWh[row * 64 + lane + 32];
        float ps = fmaf(v0, a0, v1 * a1);
        float pd = fmaf(v0, c0, v1 * c1);
        #pragma unroll
        for (int o = 16; o; o >>= 1) {
            ps += __shfl_xor_sync(0xffffffffu, ps, o);
            pd += __shfl_xor_sync(0xffffffffu, pd, o);
        }
        if (lane == 0) { s_src[row0 + row] = ps; s_dst[row0 + row] = pd; }
    }
}

// ---------------- histogram of dst degrees, both etypes (4 edges/thread) ----
__global__ __launch_bounds__(256) void hist_kernel(const int4* __restrict__ dstA4,
                                                   const int4* __restrict__ dstB4,
                                                   int* __restrict__ cnt)
{
    int i = blockIdx.x * blockDim.x + threadIdx.x;
    const int nq = N_EDGE / 4;
    if (i >= 2 * nq) return;
    bool second = i >= nq;
    int4 d = second ? dstB4[i - nq] : dstA4[i];
    int gbase = second ? N_ITEM : 0;
    atomicAdd(&cnt[gbase + d.x], 1);
    atomicAdd(&cnt[gbase + d.y], 1);
    atomicAdd(&cnt[gbase + d.z], 1);
    atomicAdd(&cnt[gbase + d.w], 1);
}

// ---------------- exclusive scan (3 kernels) ----------------
__global__ __launch_bounds__(256) void scan1_kernel(const int* __restrict__ cnt,
        int* __restrict__ offs, int* __restrict__ bsum)
{
    __shared__ int wsum[8];
    int tid = threadIdx.x;
    int base = blockIdx.x * 1024 + tid * 4;
    int v[4];
    #pragma unroll
    for (int q = 0; q < 4; q++) { int i = base + q; v[q] = (i < N_NODE2) ? cnt[i] : 0; }
    int t = v[0] + v[1] + v[2] + v[3];
    int lane = tid & 31, wid = tid >> 5;
    int inc = t;
    #pragma unroll
    for (int o = 1; o < 32; o <<= 1) { int n = __shfl_up_sync(0xffffffffu, inc, o); if (lane >= o) inc += n; }
    if (lane == 31) wsum[wid] = inc;
    __syncthreads();
    if (wid == 0) {
        int ws = (lane < 8) ? wsum[lane] : 0;
        int winc = ws;
        #pragma unroll
        for (int o = 1; o < 8; o <<= 1) { int n = __shfl_up_sync(0xffffffffu, winc, o); if (lane >= o) winc += n; }
        if (lane < 8) wsum[lane] = winc - ws;          // exclusive warp offsets
        if (lane == 7) bsum[blockIdx.x] = winc;        // block total
    }
    __syncthreads();
    int run = wsum[wid] + (inc - t);
    #pragma unroll
    for (int q = 0; q < 4; q++) { int i = base + q; if (i < N_NODE2) offs[i] = run; run += v[q]; }
}

__global__ __launch_bounds__(256) void scan2_kernel(const int* __restrict__ bsum,
                                                    int* __restrict__ boff)
{
    __shared__ int wsum[8];
    int tid = threadIdx.x;
    int v = (tid < NBLK_SCAN) ? bsum[tid] : 0;
    int lane = tid & 31, wid = tid >> 5;
    int inc = v;
    #pragma unroll
    for (int o = 1; o < 32; o <<= 1) { int n = __shfl_up_sync(0xffffffffu, inc, o); if (lane >= o) inc += n; }
    if (lane == 31) wsum[wid] = inc;
    __syncthreads();
    if (wid == 0) {
        int ws = (lane < 8) ? wsum[lane] : 0;
        int winc = ws;
        #pragma unroll
        for (int o = 1; o < 8; o <<= 1) { int n = __shfl_up_sync(0xffffffffu, winc, o); if (lane >= o) winc += n; }
        if (lane < 8) wsum[lane] = winc - ws;
    }
    __syncthreads();
    if (tid < NBLK_SCAN) boff[tid] = wsum[wid] + (inc - v);
}

__global__ __launch_bounds__(256) void scan3_kernel(int* __restrict__ offs,
        const int* __restrict__ boff, int* __restrict__ cursor)
{
    int i = blockIdx.x * blockDim.x + threadIdx.x;
    if (i >= N_NODE2) return;
    int o = offs[i] + boff[i >> 10];
    offs[i] = o;
    cursor[i] = o;
}

// --------- scatter (both etypes, 2 edges/thread): csr[pos] = (src, ex) ---------
// int2 index loads double MLP on the 4 dependent random scalar gathers.
__global__ __launch_bounds__(256) void scatter_kernel(
    const int2* __restrict__ srcA2, const int2* __restrict__ dstA2,
    const int2* __restrict__ srcB2, const int2* __restrict__ dstB2,
    const float* __restrict__ su_src, const float* __restrict__ su_dst,
    const float* __restrict__ si_src, const float* __restrict__ si_dst,
    int* __restrict__ cursor, float2* __restrict__ csr)
{
    int t = blockIdx.x * blockDim.x + threadIdx.x;
    const int nh = N_EDGE / 2;
    if (t >= 2 * nh) return;
    bool second = t >= nh;
    int e2 = second ? t - nh : t;
    int2 s2 = second ? srcB2[e2] : srcA2[e2];
    int2 d2 = second ? dstB2[e2] : dstA2[e2];
    const float* ssrc = second ? si_src : su_src;
    const float* sdst = second ? su_dst : si_dst;
    int gbase = second ? N_ITEM : 0;

    float vs0 = ssrc[s2.x], vs1 = ssrc[s2.y];
    float vd0 = sdst[d2.x], vd1 = sdst[d2.y];
    float v0 = vs0 + vd0;  v0 = v0 > 0.f ? v0 : NEG_SLOPE * v0;
    float v1 = vs1 + vd1;  v1 = v1 > 0.f ? v1 : NEG_SLOPE * v1;
    float ex0 = __expf(v0), ex1 = __expf(v1);

    int pos0 = atomicAdd(&cursor[gbase + d2.x], 1);
    int pos1 = atomicAdd(&cursor[gbase + d2.y], 1);
    csr[pos0] = make_float2(__int_as_float(s2.x), ex0);
    csr[pos1] = make_float2(__int_as_float(s2.y), ex1);
}

// --------- aggregate: warp per dst node; unroll-8 inner groups (R7 measured-best) --------
__global__ __launch_bounds__(256) void agg_kernel(
    const int* __restrict__ offs, const float2* __restrict__ csr,
    const float2* __restrict__ Whu2, const float2* __restrict__ Whi2,
    float2* __restrict__ out2)
{
    int g = (blockIdx.x * 256 + threadIdx.x) >> 5;
    int lane = threadIdx.x & 31;
    if (g >= N_NODE2) return;

    int beg = offs[g];
    int end = (g == N_NODE2 - 1) ? N_EDGE2 : offs[g + 1];
    const float2* Wh2 = (g < N_ITEM) ? Whu2 : Whi2;            // item-dst <- user src
    int orow = (g < N_ITEM) ? (N_USER + g) : (g - N_ITEM);

    float2 acc = make_float2(0.f, 0.f);
    float den = 0.f;

    for (int k0 = beg; k0 < end; k0 += 32) {
        int k = k0 + lane;
        float2 p = (k < end) ? csr[k] : make_float2(0.f, 0.f);  // pad: s=0(valid), ex=0
        int   s  = __float_as_int(p.x);
        float ex = p.y;
        int m = end - k0; if (m > 32) m = 32;
        for (int j0 = 0; j0 < m; j0 += 8) {
            #pragma unroll
            for (int jj = 0; jj < 8; jj++) {
                int   sj = __shfl_sync(0xffffffffu, s,  j0 + jj);
                float ej = __shfl_sync(0xffffffffu, ex, j0 + jj);
                if (ej != 0.f) {
                    float2 z = Wh2[(size_t)sj * 32 + lane];
                    acc.x = fmaf(ej, z.x, acc.x);
                    acc.y = fmaf(ej, z.y, acc.y);
                    den += ej;
                }
            }
        }
    }
    if (end > beg) {
        float inv = 1.f / den;
        acc.x *= inv; acc.y *= inv;
    }
    out2[(size_t)orow * 32 + lane] = acc;
}

// ---------------- launch ----------------
extern "C" void kernel_launch(void* const* d_in, const int* in_sizes, int n_in,
                              void* d_out, int out_size)
{
    const float* feat_user = (const float*)d_in[0];
    const float* feat_item = (const float*)d_in[1];
    const float* W_user    = (const float*)d_in[2];
    const float* b_user    = (const float*)d_in[3];
    const float* W_item    = (const float*)d_in[4];
    const float* b_item    = (const float*)d_in[5];
    const float* attn_w    = (const float*)d_in[6];
    const int*   src_u2i   = (const int*)d_in[7];
    const int*   dst_u2i   = (const int*)d_in[8];
    const int*   src_i2u   = (const int*)d_in[9];
    const int*   dst_i2u   = (const int*)d_in[10];
    float* out = (float*)d_out;

    // true DEVICE addresses of __device__ globals (host-shadow/ATS trap!)
    float *Wh_user, *Wh_item, *su_src, *su_dst, *si_src, *si_dst;
    float2 *csr;
    int *cnt, *offs, *cursor, *bsum, *boff;
    cudaGetSymbolAddress((void**)&Wh_user, g_Wh_user);
    cudaGetSymbolAddress((void**)&Wh_item, g_Wh_item);
    cudaGetSymbolAddress((void**)&su_src,  g_su_src);
    cudaGetSymbolAddress((void**)&su_dst,  g_su_dst);
    cudaGetSymbolAddress((void**)&si_src,  g_si_src);
    cudaGetSymbolAddress((void**)&si_dst,  g_si_dst);
    cudaGetSymbolAddress((void**)&cnt,     g_cnt);
    cudaGetSymbolAddress((void**)&offs,    g_offs);
    cudaGetSymbolAddress((void**)&cursor,  g_cursor);
    cudaGetSymbolAddress((void**)&bsum,    g_bsum);
    cudaGetSymbolAddress((void**)&boff,    g_boff);
    cudaGetSymbolAddress((void**)&csr,     g_csr);

    zero_kernel<<<(N_NODE2 + 255) / 256, 256>>>(cnt);

    linear_attn_kernel<<<N_USER / LROWS, 256>>>(feat_user, W_user, b_user, attn_w,
                                                Wh_user, su_src, su_dst);
    linear_attn_kernel<<<N_ITEM / LROWS, 256>>>(feat_item, W_item, b_item, attn_w,
                                                Wh_item, si_src, si_dst);

    hist_kernel<<<(2 * (N_EDGE / 4) + 255) / 256, 256>>>(
        (const int4*)dst_u2i, (const int4*)dst_i2u, cnt);

    scan1_kernel<<<NBLK_SCAN, 256>>>(cnt, offs, bsum);
    scan2_kernel<<<1, 256>>>(bsum, boff);
    scan3_kernel<<<(N_NODE2 + 255) / 256, 256>>>(offs, boff, cursor);

    scatter_kernel<<<(2 * (N_EDGE / 2) + 255) / 256, 256>>>(
        (const int2*)src_u2i, (const int2*)dst_u2i,
        (const int2*)src_i2u, (const int2*)dst_i2u,
        su_src, su_dst, si_src, si_dst, cursor, csr);

    agg_kernel<<<(N_NODE2 * 32 + 255) / 256, 256>>>(offs, csr,
                                                    (const float2*)Wh_user,
                                                    (const float2*)Wh_item,
                                                    (float2*)out);
}

// round 10
// speedup vs baseline: 1.0814x; 1.0510x over previous
#include <cuda_runtime.h>

#define N_USER   100000
#define N_ITEM   100000
#define N_NODE2  200000          // combined dst space: [0,100K)=item(u2i), [100K,200K)=user(i2u)
#define N_EDGE   1600000
#define N_EDGE2  3200000
#define IN_DIM   128
#define OUT_DIM  64
#define NEG_SLOPE 0.01f
#define LROWS    32
#define NBLK_SCAN 196            // ceil(200000/1024)

// ---------------- device scratch (static, no runtime alloc) ----------------
__device__ float  g_Wh_user[(size_t)N_USER * OUT_DIM];   // 25.6 MB
__device__ float  g_Wh_item[(size_t)N_ITEM * OUT_DIM];   // 25.6 MB
__device__ float  g_su_src[N_USER];
__device__ float  g_su_dst[N_USER];
__device__ float  g_si_src[N_ITEM];
__device__ float  g_si_dst[N_ITEM];
__device__ int    g_cnt[N_NODE2];
__device__ int    g_offs[N_NODE2];
__device__ int    g_cursor[N_NODE2];
__device__ int    g_bsum[NBLK_SCAN];
__device__ int    g_boff[NBLK_SCAN];
__device__ float2 g_csr[N_EDGE2];     // packed (src_as_float, ex), 25.6 MB

// ---------------- per-replay reset: degree counters ----------------
__global__ __launch_bounds__(256) void zero_kernel(int* __restrict__ cnt)
{
    int i = blockIdx.x * blockDim.x + threadIdx.x;
    if (i < N_NODE2) cnt[i] = 0;
}

// ------- Wh = feat @ W + b fused with s_src/s_dst epilogue -------
// (measured-best tile: thread = 2 cols x 4 rows; at FP32 FMA floor)
__global__ __launch_bounds__(256) void linear_attn_kernel(
    const float* __restrict__ feat, const float* __restrict__ W,
    const float* __restrict__ b, const float* __restrict__ attn,
    float* __restrict__ Wh, float* __restrict__ s_src, float* __restrict__ s_dst)
{
    __shared__ float Ws[IN_DIM * OUT_DIM];   // 32 KB
    __shared__ float fs[LROWS][IN_DIM];      // 16 KB (reused for Wh tile)
    int tid = threadIdx.x;

    #pragma unroll
    for (int i = tid; i < IN_DIM * OUT_DIM; i += 256) Ws[i] = W[i];

    int row0 = blockIdx.x * LROWS;
    const float4* fsrc = reinterpret_cast<const float4*>(feat + (size_t)row0 * IN_DIM);
    float4* fdst = reinterpret_cast<float4*>(&fs[0][0]);
    #pragma unroll
    for (int i = tid; i < LROWS * IN_DIM / 4; i += 256) fdst[i] = fsrc[i];
    __syncthreads();

    int cg = tid & 31;   // column pair index
    int rg = tid >> 5;   // row group (4 rows)
    const float2* Ws2 = reinterpret_cast<const float2*>(Ws);
    float2 acc[4] = {{0.f,0.f},{0.f,0.f},{0.f,0.f},{0.f,0.f}};

    #pragma unroll 8
    for (int k = 0; k < IN_DIM; k++) {
        float2 w = Ws2[k * 32 + cg];
        #pragma unroll
        for (int r = 0; r < 4; r++) {
            float f = fs[rg * 4 + r][k];
            acc[r].x = fmaf(f, w.x, acc[r].x);
            acc[r].y = fmaf(f, w.y, acc[r].y);
        }
    }

    float2 b2 = reinterpret_cast<const float2*>(b)[cg];
    __syncthreads();   // done reading fs; reuse as Wh tile
    float2* sWh2 = reinterpret_cast<float2*>(&fs[0][0]);   // [32][32] float2
    #pragma unroll
    for (int r = 0; r < 4; r++) {
        acc[r].x += b2.x; acc[r].y += b2.y;
        int row = rg * 4 + r;
        reinterpret_cast<float2*>(Wh)[(size_t)(row0 + row) * 32 + cg] = acc[r];
        sWh2[row * 32 + cg] = acc[r];
    }
    __syncthreads();

    // epilogue: 8 warps x 4 rows
    int wid = tid >> 5, lane = tid & 31;
    float a0 = attn[lane],      a1 = attn[lane + 32];
    float c0 = attn[64 + lane], c1 = attn[96 + lane];
    const float* sWh = &fs[0][0];
    #pragma unroll
    for (int rr = 0; rr < 4; rr++) {
        int row = wid * 4 + rr;
        float v0 = sWh[row * 64 + lane];
        float v1 = sWh[row * 64 + lane + 32];
        float ps = fmaf(v0, a0, v1 * a1);
        float pd = fmaf(v0, c0, v1 * c1);
        #pragma unroll
        for (int o = 16; o; o >>= 1) {
            ps += __shfl_xor_sync(0xffffffffu, ps, o);
            pd += __shfl_xor_sync(0xffffffffu, pd, o);
        }
        if (lane == 0) { s_src[row0 + row] = ps; s_dst[row0 + row] = pd; }
    }
}

// ---------------- histogram of dst degrees, both etypes (4 edges/thread) ----
__global__ __launch_bounds__(256) void hist_kernel(const int4* __restrict__ dstA4,
                                                   const int4* __restrict__ dstB4,
                                                   int* __restrict__ cnt)
{
    int i = blockIdx.x * blockDim.x + threadIdx.x;
    const int nq = N_EDGE / 4;
    if (i >= 2 * nq) return;
    bool second = i >= nq;
    int4 d = second ? dstB4[i - nq] : dstA4[i];
    int gbase = second ? N_ITEM : 0;
    atomicAdd(&cnt[gbase + d.x], 1);
    atomicAdd(&cnt[gbase + d.y], 1);
    atomicAdd(&cnt[gbase + d.z], 1);
    atomicAdd(&cnt[gbase + d.w], 1);
}

// ---------------- exclusive scan (3 kernels) ----------------
__global__ __launch_bounds__(256) void scan1_kernel(const int* __restrict__ cnt,
        int* __restrict__ offs, int* __restrict__ bsum)
{
    __shared__ int wsum[8];
    int tid = threadIdx.x;
    int base = blockIdx.x * 1024 + tid * 4;
    int v[4];
    #pragma unroll
    for (int q = 0; q < 4; q++) { int i = base + q; v[q] = (i < N_NODE2) ? cnt[i] : 0; }
    int t = v[0] + v[1] + v[2] + v[3];
    int lane = tid & 31, wid = tid >> 5;
    int inc = t;
    #pragma unroll
    for (int o = 1; o < 32; o <<= 1) { int n = __shfl_up_sync(0xffffffffu, inc, o); if (lane >= o) inc += n; }
    if (lane == 31) wsum[wid] = inc;
    __syncthreads();
    if (wid == 0) {
        int ws = (lane < 8) ? wsum[lane] : 0;
        int winc = ws;
        #pragma unroll
        for (int o = 1; o < 8; o <<= 1) { int n = __shfl_up_sync(0xffffffffu, winc, o); if (lane >= o) winc += n; }
        if (lane < 8) wsum[lane] = winc - ws;          // exclusive warp offsets
        if (lane == 7) bsum[blockIdx.x] = winc;        // block total
    }
    __syncthreads();
    int run = wsum[wid] + (inc - t);
    #pragma unroll
    for (int q = 0; q < 4; q++) { int i = base + q; if (i < N_NODE2) offs[i] = run; run += v[q]; }
}

__global__ __launch_bounds__(256) void scan2_kernel(const int* __restrict__ bsum,
                                                    int* __restrict__ boff)
{
    __shared__ int wsum[8];
    int tid = threadIdx.x;
    int v = (tid < NBLK_SCAN) ? bsum[tid] : 0;
    int lane = tid & 31, wid = tid >> 5;
    int inc = v;
    #pragma unroll
    for (int o = 1; o < 32; o <<= 1) { int n = __shfl_up_sync(0xffffffffu, inc, o); if (lane >= o) inc += n; }
    if (lane == 31) wsum[wid] = inc;
    __syncthreads();
    if (wid == 0) {
        int ws = (lane < 8) ? wsum[lane] : 0;
        int winc = ws;
        #pragma unroll
        for (int o = 1; o < 8; o <<= 1) { int n = __shfl_up_sync(0xffffffffu, winc, o); if (lane >= o) winc += n; }
        if (lane < 8) wsum[lane] = winc - ws;
    }
    __syncthreads();
    if (tid < NBLK_SCAN) boff[tid] = wsum[wid] + (inc - v);
}

__global__ __launch_bounds__(256) void scan3_kernel(int* __restrict__ offs,
        const int* __restrict__ boff, int* __restrict__ cursor)
{
    int i = blockIdx.x * blockDim.x + threadIdx.x;
    if (i >= N_NODE2) return;
    int o = offs[i] + boff[i >> 10];
    offs[i] = o;
    cursor[i] = o;
}

// --------- scatter (both etypes, 2 edges/thread): csr[pos] = (src, ex) ---------
__global__ __launch_bounds__(256) void scatter_kernel(
    const int2* __restrict__ srcA2, const int2* __restrict__ dstA2,
    const int2* __restrict__ srcB2, const int2* __restrict__ dstB2,
    const float* __restrict__ su_src, const float* __restrict__ su_dst,
    const float* __restrict__ si_src, const float* __restrict__ si_dst,
    int* __restrict__ cursor, float2* __restrict__ csr)
{
    int t = blockIdx.x * blockDim.x + threadIdx.x;
    const int nh = N_EDGE / 2;
    if (t >= 2 * nh) return;
    bool second = t >= nh;
    int e2 = second ? t - nh : t;
    int2 s2 = second ? srcB2[e2] : srcA2[e2];
    int2 d2 = second ? dstB2[e2] : dstA2[e2];
    const float* ssrc = second ? si_src : su_src;
    const float* sdst = second ? su_dst : si_dst;
    int gbase = second ? N_ITEM : 0;

    float vs0 = ssrc[s2.x], vs1 = ssrc[s2.y];
    float vd0 = sdst[d2.x], vd1 = sdst[d2.y];
    float v0 = vs0 + vd0;  v0 = v0 > 0.f ? v0 : NEG_SLOPE * v0;
    float v1 = vs1 + vd1;  v1 = v1 > 0.f ? v1 : NEG_SLOPE * v1;
    float ex0 = __expf(v0), ex1 = __expf(v1);

    int pos0 = atomicAdd(&cursor[gbase + d2.x], 1);
    int pos1 = atomicAdd(&cursor[gbase + d2.y], 1);
    csr[pos0] = make_float2(__int_as_float(s2.x), ex0);
    csr[pos1] = make_float2(__int_as_float(s2.y), ex1);
}

// --------- aggregate: warp per dst node; unroll-8 inner groups (measured-best) --------
__global__ __launch_bounds__(256) void agg_kernel(
    const int* __restrict__ offs, const float2* __restrict__ csr,
    const float2* __restrict__ Whu2, const float2* __restrict__ Whi2,
    float2* __restrict__ out2)
{
    int g = (blockIdx.x * 256 + threadIdx.x) >> 5;
    int lane = threadIdx.x & 31;
    if (g >= N_NODE2) return;

    int beg = offs[g];
    int end = (g == N_NODE2 - 1) ? N_EDGE2 : offs[g + 1];
    const float2* Wh2 = (g < N_ITEM) ? Whu2 : Whi2;            // item-dst <- user src
    int orow = (g < N_ITEM) ? (N_USER + g) : (g - N_ITEM);

    float2 acc = make_float2(0.f, 0.f);
    float den = 0.f;

    for (int k0 = beg; k0 < end; k0 += 32) {
        int k = k0 + lane;
        float2 p = (k < end) ? csr[k] : make_float2(0.f, 0.f);  // pad: s=0(valid), ex=0
        int   s  = __float_as_int(p.x);
        float ex = p.y;
        int m = end - k0; if (m > 32) m = 32;
        for (int j0 = 0; j0 < m; j0 += 8) {
            #pragma unroll
            for (int jj = 0; jj < 8; jj++) {
                int   sj = __shfl_sync(0xffffffffu, s,  j0 + jj);
                float ej = __shfl_sync(0xffffffffu, ex, j0 + jj);
                if (ej != 0.f) {
                    float2 z = Wh2[(size_t)sj * 32 + lane];
                    acc.x = fmaf(ej, z.x, acc.x);
                    acc.y = fmaf(ej, z.y, acc.y);
                    den += ej;
                }
            }
        }
    }
    if (end > beg) {
        float inv = 1.f / den;
        acc.x *= inv; acc.y *= inv;
    }
    out2[(size_t)orow * 32 + lane] = acc;
}

// ---------------- launch: forked-capture schedule ----------------
// Dependency truth: {zero->hist->scan1->scan2->scan3} needs only edge indices;
// {linear_user, linear_item} need only feats/weights. Independent until scatter.
// Fork them onto side streams so the captured graph runs them concurrently —
// the CSR-build chain (~34us) hides under the FMA-bound linears (~96us).
// Streams/events are created lazily on the first (uncaptured) correctness call;
// no device memory is allocated; every call records the same graph structure.
extern "C" void kernel_launch(void* const* d_in, const int* in_sizes, int n_in,
                              void* d_out, int out_size)
{
    const float* feat_user = (const float*)d_in[0];
    const float* feat_item = (const float*)d_in[1];
    const float* W_user    = (const float*)d_in[2];
    const float* b_user    = (const float*)d_in[3];
    const float* W_item    = (const float*)d_in[4];
    const float* b_item    = (const float*)d_in[5];
    const float* attn_w    = (const float*)d_in[6];
    const int*   src_u2i   = (const int*)d_in[7];
    const int*   dst_u2i   = (const int*)d_in[8];
    const int*   src_i2u   = (const int*)d_in[9];
    const int*   dst_i2u   = (const int*)d_in[10];
    float* out = (float*)d_out;

    // true DEVICE addresses of __device__ globals (host-shadow/ATS trap!)
    float *Wh_user, *Wh_item, *su_src, *su_dst, *si_src, *si_dst;
    float2 *csr;
    int *cnt, *offs, *cursor, *bsum, *boff;
    cudaGetSymbolAddress((void**)&Wh_user, g_Wh_user);
    cudaGetSymbolAddress((void**)&Wh_item, g_Wh_item);
    cudaGetSymbolAddress((void**)&su_src,  g_su_src);
    cudaGetSymbolAddress((void**)&su_dst,  g_su_dst);
    cudaGetSymbolAddress((void**)&si_src,  g_si_src);
    cudaGetSymbolAddress((void**)&si_dst,  g_si_dst);
    cudaGetSymbolAddress((void**)&cnt,     g_cnt);
    cudaGetSymbolAddress((void**)&offs,    g_offs);
    cudaGetSymbolAddress((void**)&cursor,  g_cursor);
    cudaGetSymbolAddress((void**)&bsum,    g_bsum);
    cudaGetSymbolAddress((void**)&boff,    g_boff);
    cudaGetSymbolAddress((void**)&csr,     g_csr);

    static cudaStream_t sB = nullptr, sC = nullptr;
    static cudaEvent_t ev0 = nullptr, evB = nullptr, evC = nullptr;
    if (sB == nullptr) {
        cudaStreamCreateWithFlags(&sB, cudaStreamNonBlocking);
        cudaStreamCreateWithFlags(&sC, cudaStreamNonBlocking);
        cudaEventCreateWithFlags(&ev0, cudaEventDisableTiming);
        cudaEventCreateWithFlags(&evB, cudaEventDisableTiming);
        cudaEventCreateWithFlags(&evC, cudaEventDisableTiming);
    }

    // fork point on the (possibly capturing) default stream
    cudaEventRecord(ev0, 0);

    // branch B: CSR build chain
    cudaStreamWaitEvent(sB, ev0, 0);
    zero_kernel<<<(N_NODE2 + 255) / 256, 256, 0, sB>>>(cnt);
    hist_kernel<<<(2 * (N_EDGE / 4) + 255) / 256, 256, 0, sB>>>(
        (const int4*)dst_u2i, (const int4*)dst_i2u, cnt);
    scan1_kernel<<<NBLK_SCAN, 256, 0, sB>>>(cnt, offs, bsum);
    scan2_kernel<<<1, 256, 0, sB>>>(bsum, boff);
    scan3_kernel<<<(N_NODE2 + 255) / 256, 256, 0, sB>>>(offs, boff, cursor);
    cudaEventRecord(evB, sB);

    // branch C: item linear (overlaps user linear's wave tail)
    cudaStreamWaitEvent(sC, ev0, 0);
    linear_attn_kernel<<<N_ITEM / LROWS, 256, 0, sC>>>(feat_item, W_item, b_item, attn_w,
                                                       Wh_item, si_src, si_dst);
    cudaEventRecord(evC, sC);

    // main branch: user linear
    linear_attn_kernel<<<N_USER / LROWS, 256>>>(feat_user, W_user, b_user, attn_w,
                                                Wh_user, su_src, su_dst);

    // join: scatter needs scalars (main, C) + cursor (B)
    cudaStreamWaitEvent(0, evB, 0);
    cudaStreamWaitEvent(0, evC, 0);

    scatter_kernel<<<(2 * (N_EDGE / 2) + 255) / 256, 256>>>(
        (const int2*)src_u2i, (const int2*)dst_u2i,
        (const int2*)src_i2u, (const int2*)dst_i2u,
        su_src, su_dst, si_src, si_dst, cursor, csr);

    agg_kernel<<<(N_NODE2 * 32 + 255) / 256, 256>>>(offs, csr,
                                                    (const float2*)Wh_user,
                                                    (const float2*)Wh_item,
                                                    (float2*)out);
}